// round 1
// baseline (speedup 1.0000x reference)
#include <cuda_runtime.h>

#define B_ 8
#define A_ 65536
#define O_ 64
#define C_ 81
#define N_BA (B_ * A_)

#define NEG_INF __int_as_float(0xff800000)

struct GState {
    int P;
    int Nneg;
    int k;
    int remaining;
    unsigned prefix;
    unsigned mask;
    float box_sum;
    float posce_sum;
    float sum_gt;
    unsigned hist[256];
};
__device__ GState g;
__device__ float g_negce[N_BA];

__device__ __forceinline__ unsigned f2key(float f) {
    unsigned u = __float_as_uint(f);
    return (u & 0x80000000u) ? ~u : (u | 0x80000000u);
}
__device__ __forceinline__ float key2f(unsigned k) {
    unsigned u = (k & 0x80000000u) ? (k & 0x7FFFFFFFu) : ~k;
    return __uint_as_float(u);
}

__global__ void init_kernel() {
    int t = threadIdx.x;
    if (t == 0) {
        g.P = 0; g.Nneg = 0; g.k = 0; g.remaining = 0;
        g.prefix = 0u; g.mask = 0u;
        g.box_sum = 0.f; g.posce_sum = 0.f; g.sum_gt = 0.f;
    }
    g.hist[t] = 0u;
}

__global__ void __launch_bounds__(128) main_kernel(
    const float* __restrict__ pred_boxes,
    const float* __restrict__ pred_classes,
    const float* __restrict__ gt_boxes,
    const int*   __restrict__ labels,
    const float* __restrict__ anchors)
{
    __shared__ float s_cls[128 * C_];       // 41472 B
    __shared__ float4 s_gt[O_];
    __shared__ int s_lab[O_];

    const int tid = threadIdx.x;
    const int idx = blockIdx.x * 128 + tid;
    const int b = idx >> 16;                // A_ = 65536
    const int a = idx & (A_ - 1);

    if (tid < O_) {
        s_gt[tid] = ((const float4*)gt_boxes)[b * O_ + tid];
        s_lab[tid] = labels[b * O_ + tid];
    }
    // Stage this block's contiguous class-logit region (coalesced)
    const float* cls_blk = pred_classes + (size_t)blockIdx.x * (128 * C_);
    #pragma unroll
    for (int i = 0; i < C_; i++)
        s_cls[i * 128 + tid] = __ldg(cls_blk + i * 128 + tid);
    __syncthreads();

    const float4 an = ((const float4*)anchors)[a];
    const float a_area = (an.z - an.x) * (an.w - an.y);

    // Pass 1: max IoU over valid gts
    float mo = -1.0f;
    for (int o = 0; o < O_; o++) {
        if (s_lab[o] < 0) continue;
        float4 gb = s_gt[o];
        float lx = fmaxf(an.x, gb.x), ly = fmaxf(an.y, gb.y);
        float rx = fminf(an.z, gb.z), ry = fminf(an.w, gb.w);
        float w = fmaxf(rx - lx, 0.f), h = fmaxf(ry - ly, 0.f);
        float inter = w * h;
        float ga = (gb.z - gb.x) * (gb.w - gb.y);
        float iou = inter / (a_area + ga - inter);
        mo = fmaxf(mo, iou);
    }

    // logsumexp over this row's 81 logits (3-way online softmax, conflict-free smem)
    const float* row = &s_cls[tid * C_];
    float m0 = -1e30f, m1 = -1e30f, m2 = -1e30f;
    float s0 = 0.f, s1 = 0.f, s2 = 0.f;
    #pragma unroll
    for (int c = 0; c < C_; c += 3) {
        float x0 = row[c], x1 = row[c + 1], x2 = row[c + 2];
        float n0 = fmaxf(m0, x0); s0 = s0 * __expf(m0 - n0) + __expf(x0 - n0); m0 = n0;
        float n1 = fmaxf(m1, x1); s1 = s1 * __expf(m1 - n1) + __expf(x1 - n1); m1 = n1;
        float n2 = fmaxf(m2, x2); s2 = s2 * __expf(m2 - n2) + __expf(x2 - n2); m2 = n2;
    }
    // c = 81 loop covers 0..80 exactly (81 = 27*3)
    float M = fmaxf(m0, fmaxf(m1, m2));
    float S = s0 * __expf(m0 - M) + s1 * __expf(m1 - M) + s2 * __expf(m2 - M);
    float lse = M + __logf(S);

    bool isneg = (mo < 0.5f);
    unsigned ball = __ballot_sync(0xFFFFFFFFu, isneg);
    if ((tid & 31) == 0) atomicAdd(&g.Nneg, __popc(ball));

    if (isneg) {
        g_negce[idx] = lse - row[0];
    } else {
        g_negce[idx] = NEG_INF;
        if (mo > 0.5f) {
            // Positive anchor: find matching gt(s), accumulate box + pos-CE losses
            float4 pbv = ((const float4*)pred_boxes)[idx];
            float a_cx = 0.5f * (an.x + an.z), a_cy = 0.5f * (an.y + an.w);
            float a_w = an.z - an.x, a_h = an.w - an.y;
            int np = 0; float bsum = 0.f, csum = 0.f;
            for (int o = 0; o < O_; o++) {
                if (s_lab[o] < 0) continue;
                float4 gb = s_gt[o];
                float lx = fmaxf(an.x, gb.x), ly = fmaxf(an.y, gb.y);
                float rx = fminf(an.z, gb.z), ry = fminf(an.w, gb.w);
                float w = fmaxf(rx - lx, 0.f), h = fmaxf(ry - ly, 0.f);
                float inter = w * h;
                float ga = (gb.z - gb.x) * (gb.w - gb.y);
                float iou = inter / (a_area + ga - inter);
                if (iou > 0.5f && fabsf(mo - iou) < 1e-6f) {
                    float g_cx = 0.5f * (gb.x + gb.z), g_cy = 0.5f * (gb.y + gb.w);
                    float g_w = gb.z - gb.x, g_h = gb.w - gb.y;
                    float tx = (g_cx - a_cx) / (0.1f * a_w);
                    float ty = (g_cy - a_cy) / (0.1f * a_h);
                    float tw = logf(g_w / a_w) / 0.2f;
                    float th = logf(g_h / a_h) / 0.2f;
                    float d, sl = 0.f;
                    d = fabsf(pbv.x - tx); sl += (d < 1.f) ? 0.5f * d * d : d - 0.5f;
                    d = fabsf(pbv.y - ty); sl += (d < 1.f) ? 0.5f * d * d : d - 0.5f;
                    d = fabsf(pbv.z - tw); sl += (d < 1.f) ? 0.5f * d * d : d - 0.5f;
                    d = fabsf(pbv.w - th); sl += (d < 1.f) ? 0.5f * d * d : d - 0.5f;
                    bsum += sl;
                    csum += lse - row[s_lab[o]];
                    np++;
                }
            }
            if (np) {
                atomicAdd(&g.P, np);
                atomicAdd(&g.box_sum, bsum);
                atomicAdd(&g.posce_sum, csum);
            }
        }
    }
}

__global__ void kcompute_kernel() {
    int k = min(10 * g.P, g.Nneg);
    g.k = k;
    g.remaining = k;
}

__global__ void hist_kernel(int shift) {
    __shared__ unsigned sh[256];
    sh[threadIdx.x] = 0u;
    __syncthreads();
    unsigned msk = g.mask, pfx = g.prefix;
    int i = blockIdx.x * 256 + threadIdx.x;
    unsigned key = f2key(g_negce[i]);
    if ((key & msk) == pfx)
        atomicAdd(&sh[(key >> shift) & 255u], 1u);
    __syncthreads();
    unsigned v = sh[threadIdx.x];
    if (v) atomicAdd(&g.hist[threadIdx.x], v);
}

__global__ void pick_kernel(int shift) {
    if (threadIdx.x == 0) {
        int rem = g.remaining;
        if (rem > 0) {
            int cum = 0;
            for (int i = 255; i >= 0; i--) {
                int h = (int)g.hist[i];
                cum += h;
                if (cum >= rem) {
                    g.remaining = rem - (cum - h);
                    g.prefix |= ((unsigned)i) << shift;
                    g.mask |= 0xFFu << shift;
                    break;
                }
            }
        }
    }
    __syncthreads();
    g.hist[threadIdx.x] = 0u;
}

__global__ void sumtop_kernel() {
    __shared__ float ssum[256];
    float v = 0.f;
    if (g.k > 0) {
        int i = blockIdx.x * 256 + threadIdx.x;
        float x = g_negce[i];
        if (f2key(x) > g.prefix) v = x;
    }
    ssum[threadIdx.x] = v;
    __syncthreads();
    for (int s = 128; s > 0; s >>= 1) {
        if (threadIdx.x < s) ssum[threadIdx.x] += ssum[threadIdx.x + s];
        __syncthreads();
    }
    if (threadIdx.x == 0 && ssum[0] != 0.f) atomicAdd(&g.sum_gt, ssum[0]);
}

__global__ void final_kernel(float* out) {
    int P = g.P;
    int k = g.k;
    float boxes = g.box_sum / (float)(P > 0 ? P : 1);
    int n_sel = P + k;
    float classes = 0.f;
    if (n_sel > 0) {
        float sum_top = 0.f;
        if (k > 0) sum_top = g.sum_gt + (float)g.remaining * key2f(g.prefix);
        float ns = (float)n_sel;
        classes = (g.posce_sum + sum_top) / (ns * ns);
    }
    out[0] = boxes;
    out[1] = classes;
    out[2] = boxes + classes;
}

extern "C" void kernel_launch(void* const* d_in, const int* in_sizes, int n_in,
                              void* d_out, int out_size) {
    const float* pred_boxes   = (const float*)d_in[0];
    const float* pred_classes = (const float*)d_in[1];
    const float* gt_boxes     = (const float*)d_in[2];
    const int*   labels       = (const int*)d_in[3];
    const float* anchors      = (const float*)d_in[4];
    float* out = (float*)d_out;

    init_kernel<<<1, 256>>>();
    main_kernel<<<N_BA / 128, 128>>>(pred_boxes, pred_classes, gt_boxes, labels, anchors);
    kcompute_kernel<<<1, 1>>>();
    for (int shift = 24; shift >= 0; shift -= 8) {
        hist_kernel<<<N_BA / 256, 256>>>(shift);
        pick_kernel<<<1, 256>>>(shift);
    }
    sumtop_kernel<<<N_BA / 256, 256>>>();
    final_kernel<<<1, 1>>>(out);
}

// round 3
// speedup vs baseline: 1.8219x; 1.8219x over previous
#include <cuda_runtime.h>

#define B_ 8
#define A_ 65536
#define O_ 64
#define C_ 81
#define N_BA (B_ * A_)
#define NBINS 4096

#define NEG_INF __int_as_float(0xff800000)

struct GState {
    int P;
    int Nneg;
    int k;
    int remaining;
    unsigned prefix;
    unsigned mask;
    unsigned done;
    float box_sum;
    float posce_sum;
    float sum_gt;
    unsigned hist[NBINS];
};
__device__ GState g;
__device__ float g_negce[N_BA];

__device__ __forceinline__ unsigned f2key(float f) {
    unsigned u = __float_as_uint(f);
    return (u & 0x80000000u) ? ~u : (u | 0x80000000u);
}
__device__ __forceinline__ float key2f(unsigned k) {
    unsigned u = (k & 0x80000000u) ? (k & 0x7FFFFFFFu) : ~k;
    return __uint_as_float(u);
}

__global__ void init_kernel() {
    int i = blockIdx.x * 1024 + threadIdx.x;
    if (i < NBINS) g.hist[i] = 0u;
    if (i == 0) {
        g.P = 0; g.Nneg = 0; g.k = 0; g.remaining = 0;
        g.prefix = 0u; g.mask = 0u; g.done = 0u;
        g.box_sum = 0.f; g.posce_sum = 0.f; g.sum_gt = 0.f;
    }
}

__global__ void __launch_bounds__(128) main_kernel(
    const float* __restrict__ pred_boxes,
    const float* __restrict__ pred_classes,
    const float* __restrict__ gt_boxes,
    const int*   __restrict__ labels,
    const float* __restrict__ anchors)
{
    __shared__ float s_cls[128 * C_];   // 41472 B
    __shared__ float4 s_gt[O_];
    __shared__ float s_ga[O_];
    __shared__ int s_lab[O_];

    const int tid = threadIdx.x;
    const int idx = blockIdx.x * 128 + tid;
    const int b = blockIdx.x >> 9;          // 512 blocks per batch
    const int a = idx & (A_ - 1);

    if (tid < O_) {
        float4 gbv = ((const float4*)gt_boxes)[b * O_ + tid];
        int lab = labels[b * O_ + tid];
        if (lab < 0) gbv = make_float4(-1e9f, -1e9f, -1e9f, -1e9f);
        s_gt[tid] = gbv;
        s_ga[tid] = (gbv.z - gbv.x) * (gbv.w - gbv.y);
        s_lab[tid] = lab;
    }
    // Coalesced float4 staging of this block's 128x81 logit region (streaming)
    {
        const float4* src = (const float4*)(pred_classes + (size_t)blockIdx.x * (128 * C_));
        float4* dst = (float4*)s_cls;
        #pragma unroll 4
        for (int i = tid; i < (128 * C_) / 4; i += 128) dst[i] = __ldcs(src + i);
    }
    __syncthreads();

    const float4 an = ((const float4*)anchors)[a];
    const float a_area = (an.z - an.x) * (an.w - an.y);

    // Pass 1: max IoU over gts (branch-free; invalid gts yield iou = 0)
    float mo = -1.0f;
    #pragma unroll 4
    for (int o = 0; o < O_; o++) {
        float4 gb = s_gt[o];
        float lx = fmaxf(an.x, gb.x), ly = fmaxf(an.y, gb.y);
        float rx = fminf(an.z, gb.z), ry = fminf(an.w, gb.w);
        float w = fmaxf(rx - lx, 0.f), h = fmaxf(ry - ly, 0.f);
        float inter = w * h;
        float iou = __fdividef(inter, a_area + s_ga[o] - inter);
        mo = fmaxf(mo, iou);
    }

    // Two-pass logsumexp over the 81 logits of this row
    const float* row = &s_cls[tid * C_];
    float M = -1e30f;
    #pragma unroll 3
    for (int c = 0; c < C_; c++) M = fmaxf(M, row[c]);
    float S = 0.f;
    #pragma unroll 3
    for (int c = 0; c < C_; c++) S += __expf(row[c] - M);
    float lse = M + __logf(S);

    bool isneg = (mo < 0.5f);
    unsigned ball = __ballot_sync(0xFFFFFFFFu, isneg);
    if ((tid & 31) == 0) atomicAdd(&g.Nneg, __popc(ball));

    if (isneg) {
        g_negce[idx] = lse - row[0];
    } else {
        g_negce[idx] = NEG_INF;
        if (mo > 0.5f) {
            float4 pbv = ((const float4*)pred_boxes)[idx];
            float a_cx = 0.5f * (an.x + an.z), a_cy = 0.5f * (an.y + an.w);
            float a_w = an.z - an.x, a_h = an.w - an.y;
            int np = 0; float bsum = 0.f, csum = 0.f;
            for (int o = 0; o < O_; o++) {
                if (s_lab[o] < 0) continue;
                float4 gb = s_gt[o];
                float lx = fmaxf(an.x, gb.x), ly = fmaxf(an.y, gb.y);
                float rx = fminf(an.z, gb.z), ry = fminf(an.w, gb.w);
                float w = fmaxf(rx - lx, 0.f), h = fmaxf(ry - ly, 0.f);
                float inter = w * h;
                float iou = __fdividef(inter, a_area + s_ga[o] - inter);
                if (iou > 0.5f && fabsf(mo - iou) < 1e-6f) {
                    float g_cx = 0.5f * (gb.x + gb.z), g_cy = 0.5f * (gb.y + gb.w);
                    float g_w = gb.z - gb.x, g_h = gb.w - gb.y;
                    float tx = (g_cx - a_cx) / (0.1f * a_w);
                    float ty = (g_cy - a_cy) / (0.1f * a_h);
                    float tw = logf(g_w / a_w) / 0.2f;
                    float th = logf(g_h / a_h) / 0.2f;
                    float d, sl = 0.f;
                    d = fabsf(pbv.x - tx); sl += (d < 1.f) ? 0.5f * d * d : d - 0.5f;
                    d = fabsf(pbv.y - ty); sl += (d < 1.f) ? 0.5f * d * d : d - 0.5f;
                    d = fabsf(pbv.z - tw); sl += (d < 1.f) ? 0.5f * d * d : d - 0.5f;
                    d = fabsf(pbv.w - th); sl += (d < 1.f) ? 0.5f * d * d : d - 0.5f;
                    bsum += sl;
                    csum += lse - row[s_lab[o]];
                    np++;
                }
            }
            if (np) {
                atomicAdd(&g.P, np);
                atomicAdd(&g.box_sum, bsum);
                atomicAdd(&g.posce_sum, csum);
            }
        }
    }
}

// 12-bit radix histogram pass (4096 smem bins, warp-aggregated atomics)
__global__ void __launch_bounds__(256) hist_kernel(int shift) {
    __shared__ unsigned sh[NBINS];
    const int tid = threadIdx.x;
    for (int i = tid; i < NBINS; i += 256) sh[i] = 0u;
    __syncthreads();
    const unsigned msk = g.mask, pfx = g.prefix;
    const float4* src = (const float4*)g_negce;
    const int nv = N_BA / 4;
    const int lane = tid & 31;
    for (int i = blockIdx.x * 256 + tid; i < nv; i += gridDim.x * 256) {
        float4 v = src[i];
        float xs[4] = {v.x, v.y, v.z, v.w};
        #pragma unroll
        for (int j = 0; j < 4; j++) {
            unsigned key = f2key(xs[j]);
            bool ok = ((key & msk) == pfx);
            unsigned bin = ok ? ((key >> shift) & (NBINS - 1u)) : (NBINS + (unsigned)lane);
            unsigned m = __match_any_sync(0xFFFFFFFFu, bin);
            if (ok && (__ffs(m) - 1) == lane) atomicAdd(&sh[bin], __popc(m));
        }
    }
    __syncthreads();
    for (int i = tid; i < NBINS; i += 256) {
        unsigned v = sh[i];
        if (v) atomicAdd(&g.hist[i], v);
    }
}

// Parallel pick: suffix-scan 4096 bins with 1024 threads, select threshold digit
__global__ void __launch_bounds__(1024) pick_kernel(int shift, int first) {
    __shared__ unsigned ssum[1024];
    const int tid = threadIdx.x;
    if (first && tid == 0) {
        int kk = min(10 * g.P, g.Nneg);
        g.k = kk; g.remaining = kk;
    }
    __syncthreads();
    const int rem = g.remaining;
    const int base = tid * 4;
    unsigned h0 = g.hist[base], h1 = g.hist[base + 1], h2 = g.hist[base + 2], h3 = g.hist[base + 3];
    unsigned loc = h0 + h1 + h2 + h3;
    ssum[tid] = loc;
    __syncthreads();
    // Hillis-Steele inclusive suffix scan over 1024 thread-partials
    for (int off = 1; off < 1024; off <<= 1) {
        unsigned v = ssum[tid];
        unsigned add = (tid + off < 1024) ? ssum[tid + off] : 0u;
        __syncthreads();
        ssum[tid] = v + add;
        __syncthreads();
    }
    unsigned after = (tid < 1023) ? ssum[tid + 1] : 0u;
    if (rem > 0 && (int)after < rem && (int)(loc + after) >= rem) {
        unsigned s3 = h3 + after, s2 = h2 + s3, s1 = h1 + s2;
        int bin; unsigned snext;
        if ((int)s3 >= rem)      { bin = base + 3; snext = after; }
        else if ((int)s2 >= rem) { bin = base + 2; snext = s3; }
        else if ((int)s1 >= rem) { bin = base + 1; snext = s2; }
        else                     { bin = base;     snext = s1; }
        g.remaining = rem - (int)snext;
        g.prefix |= ((unsigned)bin) << shift;
        g.mask |= ((unsigned)(NBINS - 1)) << shift;
    }
    __syncthreads();
    g.hist[base] = 0u; g.hist[base + 1] = 0u; g.hist[base + 2] = 0u; g.hist[base + 3] = 0u;
}

// Sum of entries strictly above threshold bin + fused final reduction
__global__ void __launch_bounds__(256) sumtop_final_kernel(float* out) {
    __shared__ float ssum[256];
    const int tid = threadIdx.x;
    const int k = g.k;
    const unsigned thr = g.prefix >> 8;   // 24-bit threshold prefix
    float local = 0.f;
    if (k > 0) {
        const float4* src = (const float4*)g_negce;
        const int nv = N_BA / 4;
        for (int i = blockIdx.x * 256 + tid; i < nv; i += gridDim.x * 256) {
            float4 v = src[i];
            if ((f2key(v.x) >> 8) > thr) local += v.x;
            if ((f2key(v.y) >> 8) > thr) local += v.y;
            if ((f2key(v.z) >> 8) > thr) local += v.z;
            if ((f2key(v.w) >> 8) > thr) local += v.w;
        }
    }
    ssum[tid] = local;
    __syncthreads();
    for (int s = 128; s > 0; s >>= 1) {
        if (tid < s) ssum[tid] += ssum[tid + s];
        __syncthreads();
    }
    if (tid == 0) {
        if (ssum[0] != 0.f) atomicAdd(&g.sum_gt, ssum[0]);
        __threadfence();
        unsigned old = atomicAdd(&g.done, 1u);
        if (old == gridDim.x - 1) {
            __threadfence();
            float sg = atomicAdd(&g.sum_gt, 0.f);
            int P = g.P;
            float boxes = g.box_sum / (float)(P > 0 ? P : 1);
            int n_sel = P + k;
            float classes = 0.f;
            if (n_sel > 0) {
                float sum_top = 0.f;
                if (k > 0) {
                    float vth = key2f(g.prefix | 0x80u);  // bin midpoint
                    sum_top = sg + (float)g.remaining * vth;
                }
                float ns = (float)n_sel;
                classes = (g.posce_sum + sum_top) / (ns * ns);
            }
            out[0] = boxes;
            out[1] = classes;
            out[2] = boxes + classes;
        }
    }
}

extern "C" void kernel_launch(void* const* d_in, const int* in_sizes, int n_in,
                              void* d_out, int out_size) {
    const float* pred_boxes   = (const float*)d_in[0];
    const float* pred_classes = (const float*)d_in[1];
    const float* gt_boxes     = (const float*)d_in[2];
    const int*   labels       = (const int*)d_in[3];
    const float* anchors      = (const float*)d_in[4];
    float* out = (float*)d_out;

    init_kernel<<<4, 1024>>>();
    main_kernel<<<N_BA / 128, 128>>>(pred_boxes, pred_classes, gt_boxes, labels, anchors);
    hist_kernel<<<128, 256>>>(20);
    pick_kernel<<<1, 1024>>>(20, 1);
    hist_kernel<<<128, 256>>>(8);
    pick_kernel<<<1, 1024>>>(8, 0);
    sumtop_final_kernel<<<128, 256>>>(out);
}